// round 8
// baseline (speedup 1.0000x reference)
#include <cuda_runtime.h>
#include <cuda_fp16.h>
#include <mma.h>
#include <cstdint>
#include <cstddef>

using namespace nvcuda;

#define HIDDEN 4096
#define INTER  11008
#define MTOT   8192   // B*S = 4*2048

// ---------------- static device scratch ------------------------------------
__device__ __align__(16) __half g_wg[(size_t)INTER * HIDDEN];   // fp16 w_gate (exact)
__device__ __align__(16) __half g_wu[(size_t)INTER * HIDDEN];   // fp16 w_up   (exact)
__device__ __align__(16) __half g_wd[(size_t)HIDDEN * INTER];   // fp16 w_down (exact)
__device__ __align__(16) __half g_x [(size_t)MTOT  * HIDDEN];   // x in fp16
__device__ __align__(16) __half g_h [(size_t)MTOT  * INTER];    // hidden fp16 (silu(g)*u/16)
__device__ __align__(16) float  g_gf[(size_t)MTOT  * INTER];    // raw gate accum (unscaled)
__device__ __align__(16) float  g_uf[(size_t)MTOT  * INTER];    // raw up accum (unscaled)
__device__ __align__(16) float  g_of[(size_t)MTOT  * HIDDEN];   // raw down accum (unscaled)

// ---------------- conversion kernels ---------------------------------------
// Weights arrive as int32 (harness upcasts int8 -> int32). Values in [-128,127],
// exactly representable in fp16.
__global__ void k_i32_to_h(const int* __restrict__ in, __half* __restrict__ out, int n8) {
    int i = blockIdx.x * blockDim.x + threadIdx.x;
    if (i >= n8) return;
    int4 a = reinterpret_cast<const int4*>(in)[2 * i];
    int4 b = reinterpret_cast<const int4*>(in)[2 * i + 1];
    union { __half h[8]; float4 f; } O;
    O.h[0] = __int2half_rn(a.x); O.h[1] = __int2half_rn(a.y);
    O.h[2] = __int2half_rn(a.z); O.h[3] = __int2half_rn(a.w);
    O.h[4] = __int2half_rn(b.x); O.h[5] = __int2half_rn(b.y);
    O.h[6] = __int2half_rn(b.z); O.h[7] = __int2half_rn(b.w);
    reinterpret_cast<float4*>(out)[i] = O.f;
}

__global__ void k_f32_to_h(const float* __restrict__ in, __half* __restrict__ out, int n8) {
    int i = blockIdx.x * blockDim.x + threadIdx.x;
    if (i >= n8) return;
    float4 a = reinterpret_cast<const float4*>(in)[2 * i];
    float4 b = reinterpret_cast<const float4*>(in)[2 * i + 1];
    union { __half h[8]; float4 f; } O;
    O.h[0] = __float2half(a.x); O.h[1] = __float2half(a.y);
    O.h[2] = __float2half(a.z); O.h[3] = __float2half(a.w);
    O.h[4] = __float2half(b.x); O.h[5] = __float2half(b.y);
    O.h[6] = __float2half(b.z); O.h[7] = __float2half(b.w);
    reinterpret_cast<float4*>(out)[i] = O.f;
}

// ---------------- panel swizzle ---------------------------------------------
__device__ __forceinline__ void tile_map(int bid, int nTiles, int GM, int& m, int& n) {
    int per_panel = GM * nTiles;
    int panel = bid / per_panel;
    int rem   = bid - panel * per_panel;
    n = rem / GM;
    m = panel * GM + (rem - n * GM);
}

// ---------------- GEMM1: gate & up, raw fp32 out ----------------------------
// CTA tile 128(M) x 64(N). 8 warps = 4(M) x 2(N); each warp 32x32 = 2x2 wmma tiles.
__global__ __launch_bounds__(256, 2)
void k_gemm1(void) {
    __shared__ __half sA [128][72];
    __shared__ __half sBg[64][72];
    __shared__ __half sBu[64][72];

    const int tid  = threadIdx.x;
    const int wid  = tid >> 5;
    const int wm   = wid >> 1, wn = wid & 1;

    int mTile, nTile;
    tile_map(blockIdx.x, INTER / 64, 16, mTile, nTile);
    const int mBase = mTile * 128;
    const int nBase = nTile * 64;

    wmma::fragment<wmma::accumulator, 16, 16, 16, float> accg[2][2];
    wmma::fragment<wmma::accumulator, 16, 16, 16, float> accu[2][2];
#pragma unroll
    for (int i = 0; i < 2; i++)
#pragma unroll
        for (int j = 0; j < 2; j++) {
            wmma::fill_fragment(accg[i][j], 0.0f);
            wmma::fill_fragment(accu[i][j], 0.0f);
        }

    const int ldv = HIDDEN / 8;
    const float4* gAv  = reinterpret_cast<const float4*>(g_x)  + (size_t)mBase * ldv;
    const float4* gBgv = reinterpret_cast<const float4*>(g_wg) + (size_t)nBase * ldv;
    const float4* gBuv = reinterpret_cast<const float4*>(g_wu) + (size_t)nBase * ldv;

    for (int k0 = 0; k0 < HIDDEN; k0 += 64) {
        const int kc = k0 >> 3;
        __syncthreads();
#pragma unroll
        for (int i = 0; i < 4; i++) {
            int idx = tid + i * 256;
            int r = idx >> 3, c = idx & 7;
            *reinterpret_cast<float4*>(&sA[r][c * 8]) = gAv[(size_t)r * ldv + kc + c];
        }
#pragma unroll
        for (int i = 0; i < 2; i++) {
            int idx = tid + i * 256;
            int r = idx >> 3, c = idx & 7;
            *reinterpret_cast<float4*>(&sBg[r][c * 8]) = gBgv[(size_t)r * ldv + kc + c];
            *reinterpret_cast<float4*>(&sBu[r][c * 8]) = gBuv[(size_t)r * ldv + kc + c];
        }
        __syncthreads();

#pragma unroll
        for (int ks = 0; ks < 64; ks += 16) {
            wmma::fragment<wmma::matrix_a, 16, 16, 16, __half, wmma::row_major> af[2];
#pragma unroll
            for (int mt = 0; mt < 2; mt++)
                wmma::load_matrix_sync(af[mt], &sA[wm * 32 + mt * 16][ks], 72);
#pragma unroll
            for (int nt = 0; nt < 2; nt++) {
                // y[m][n] = sum_k x[m][k] * W[n][k]  ->  element (k, n) at sB[n][k]:
                // col_major with ld = 72.
                wmma::fragment<wmma::matrix_b, 16, 16, 16, __half, wmma::col_major> bg, bu;
                wmma::load_matrix_sync(bg, &sBg[wn * 32 + nt * 16][ks], 72);
                wmma::load_matrix_sync(bu, &sBu[wn * 32 + nt * 16][ks], 72);
#pragma unroll
                for (int mt = 0; mt < 2; mt++) {
                    wmma::mma_sync(accg[mt][nt], af[mt], bg, accg[mt][nt]);
                    wmma::mma_sync(accu[mt][nt], af[mt], bu, accu[mt][nt]);
                }
            }
        }
    }

#pragma unroll
    for (int mt = 0; mt < 2; mt++)
#pragma unroll
        for (int nt = 0; nt < 2; nt++) {
            size_t r0 = (size_t)(mBase + wm * 32 + mt * 16);
            size_t c0 = (size_t)(nBase + wn * 32 + nt * 16);
            wmma::store_matrix_sync(&g_gf[r0 * INTER + c0], accg[mt][nt], INTER, wmma::mem_row_major);
            wmma::store_matrix_sync(&g_uf[r0 * INTER + c0], accu[mt][nt], INTER, wmma::mem_row_major);
        }
}

// ---------------- elementwise SwiGLU ----------------------------------------
// h = silu(g_raw * s_gate[c]) * (u_raw * s_up[c]) / 16, fp16
__global__ void k_swiglu(const float* __restrict__ s_gate, const float* __restrict__ s_up, int n4) {
    int i = blockIdx.x * blockDim.x + threadIdx.x;
    if (i >= n4) return;
    int cb = (i % (INTER / 4)) * 4;
    float4 g = reinterpret_cast<const float4*>(g_gf)[i];
    float4 u = reinterpret_cast<const float4*>(g_uf)[i];
    float sg0 = s_gate[cb], sg1 = s_gate[cb+1], sg2 = s_gate[cb+2], sg3 = s_gate[cb+3];
    float su0 = s_up[cb],   su1 = s_up[cb+1],   su2 = s_up[cb+2],   su3 = s_up[cb+3];
    float g0 = g.x * sg0, g1 = g.y * sg1, g2 = g.z * sg2, g3 = g.w * sg3;
    float u0 = u.x * su0, u1 = u.y * su1, u2 = u.z * su2, u3 = u.w * su3;
    float h0 = (g0 / (1.f + expf(-g0))) * u0 * 0.0625f;
    float h1 = (g1 / (1.f + expf(-g1))) * u1 * 0.0625f;
    float h2 = (g2 / (1.f + expf(-g2))) * u2 * 0.0625f;
    float h3 = (g3 / (1.f + expf(-g3))) * u3 * 0.0625f;
    union { __half h[4]; uint2 v; } O;
    O.h[0] = __float2half(h0); O.h[1] = __float2half(h1);
    O.h[2] = __float2half(h2); O.h[3] = __float2half(h3);
    reinterpret_cast<uint2*>(g_h)[i] = O.v;
}

// ---------------- GEMM2: down proj, raw fp32 out ----------------------------
__global__ __launch_bounds__(256, 2)
void k_gemm2(void) {
    __shared__ __half sA[128][72];
    __shared__ __half sB[64][72];

    const int tid  = threadIdx.x;
    const int wid  = tid >> 5;
    const int wm   = wid >> 1, wn = wid & 1;

    int mTile, nTile;
    tile_map(blockIdx.x, HIDDEN / 64, 16, mTile, nTile);
    const int mBase = mTile * 128;
    const int nBase = nTile * 64;

    wmma::fragment<wmma::accumulator, 16, 16, 16, float> acc[2][2];
#pragma unroll
    for (int i = 0; i < 2; i++)
#pragma unroll
        for (int j = 0; j < 2; j++) wmma::fill_fragment(acc[i][j], 0.0f);

    const int ldv = INTER / 8;  // 1376
    const float4* gAv = reinterpret_cast<const float4*>(g_h)  + (size_t)mBase * ldv;
    const float4* gBv = reinterpret_cast<const float4*>(g_wd) + (size_t)nBase * ldv;

#pragma unroll 1
    for (int k0 = 0; k0 < INTER; k0 += 64) {
        const int kc = k0 >> 3;
        __syncthreads();
#pragma unroll
        for (int i = 0; i < 4; i++) {
            int idx = tid + i * 256;
            int r = idx >> 3, c = idx & 7;
            *reinterpret_cast<float4*>(&sA[r][c * 8]) = gAv[(size_t)r * ldv + kc + c];
        }
#pragma unroll
        for (int i = 0; i < 2; i++) {
            int idx = tid + i * 256;
            int r = idx >> 3, c = idx & 7;
            *reinterpret_cast<float4*>(&sB[r][c * 8]) = gBv[(size_t)r * ldv + kc + c];
        }
        __syncthreads();

#pragma unroll
        for (int ks = 0; ks < 64; ks += 16) {
            wmma::fragment<wmma::matrix_a, 16, 16, 16, __half, wmma::row_major> af[2];
#pragma unroll
            for (int mt = 0; mt < 2; mt++)
                wmma::load_matrix_sync(af[mt], &sA[wm * 32 + mt * 16][ks], 72);
#pragma unroll
            for (int nt = 0; nt < 2; nt++) {
                wmma::fragment<wmma::matrix_b, 16, 16, 16, __half, wmma::col_major> bf;
                wmma::load_matrix_sync(bf, &sB[wn * 32 + nt * 16][ks], 72);
#pragma unroll
                for (int mt = 0; mt < 2; mt++)
                    wmma::mma_sync(acc[mt][nt], af[mt], bf, acc[mt][nt]);
            }
        }
    }

#pragma unroll
    for (int mt = 0; mt < 2; mt++)
#pragma unroll
        for (int nt = 0; nt < 2; nt++) {
            size_t r0 = (size_t)(mBase + wm * 32 + mt * 16);
            size_t c0 = (size_t)(nBase + wn * 32 + nt * 16);
            wmma::store_matrix_sync(&g_of[r0 * HIDDEN + c0], acc[mt][nt], HIDDEN, wmma::mem_row_major);
        }
}

// ---------------- elementwise down-scale ------------------------------------
// out = raw * s_down[c] * 16  (undo hidden /16)
__global__ void k_down_scale(const float* __restrict__ s_down, float* __restrict__ out, int n4) {
    int i = blockIdx.x * blockDim.x + threadIdx.x;
    if (i >= n4) return;
    int cb = (i % (HIDDEN / 4)) * 4;
    float4 v = reinterpret_cast<const float4*>(g_of)[i];
    float4 o;
    o.x = v.x * s_down[cb]     * 16.f;
    o.y = v.y * s_down[cb + 1] * 16.f;
    o.z = v.z * s_down[cb + 2] * 16.f;
    o.w = v.w * s_down[cb + 3] * 16.f;
    reinterpret_cast<float4*>(out)[i] = o;
}

// ---------------- launch -----------------------------------------------------
// Inputs identified by element count (dict order confirmed: x first):
//   x -> 33,554,432 f32 ; s_down -> 4,096 f32 ; s_gate,s_up -> 11,008 f32
//   w_gate,w_up,w_down -> 45,088,768 elements, **int32** (harness upcasts int8)
extern "C" void kernel_launch(void* const* d_in, const int* in_sizes, int n_in,
                              void* d_out, int out_size) {
    int ix = -1, isd = -1;
    int is_[2]; int ns = 0;
    int iw_[3]; int nw = 0;
    for (int i = 0; i < n_in; i++) {
        int sz = in_sizes[i];
        if (sz == MTOT * HIDDEN)       ix = i;
        else if (sz == HIDDEN)         isd = i;
        else if (sz == INTER)          { if (ns < 2) is_[ns++] = i; }
        else if (sz == INTER * HIDDEN) { if (nw < 3) iw_[nw++] = i; }
    }
    bool dict_order = (ix == 0);
    int iwg = dict_order ? iw_[0] : iw_[1];
    int iwu = dict_order ? iw_[1] : iw_[2];
    int iwd = dict_order ? iw_[2] : iw_[0];

    const float* x  = (const float*)d_in[ix];
    const int*   wg = (const int*)  d_in[iwg];   // int32 weights
    const float* sg = (const float*)d_in[is_[0]];
    const int*   wu = (const int*)  d_in[iwu];
    const float* su = (const float*)d_in[is_[1]];
    const int*   wd = (const int*)  d_in[iwd];
    const float* sd = (const float*)d_in[isd];
    float* out = (float*)d_out;

    void *pwg, *pwu, *pwd, *px;
    cudaGetSymbolAddress(&pwg, g_wg);
    cudaGetSymbolAddress(&pwu, g_wu);
    cudaGetSymbolAddress(&pwd, g_wd);
    cudaGetSymbolAddress(&px,  g_x);

    const int nW8 = (INTER * HIDDEN) / 8;
    const int nX8 = (MTOT * HIDDEN) / 8;
    k_i32_to_h<<<(nW8 + 255) / 256, 256>>>(wg, (__half*)pwg, nW8);
    k_i32_to_h<<<(nW8 + 255) / 256, 256>>>(wu, (__half*)pwu, nW8);
    k_i32_to_h<<<(nW8 + 255) / 256, 256>>>(wd, (__half*)pwd, nW8);
    k_f32_to_h<<<(nX8 + 255) / 256, 256>>>(x, (__half*)px, nX8);

    k_gemm1<<<(MTOT / 128) * (INTER / 64), 256>>>();

    const int nH4 = (MTOT * INTER) / 4;
    k_swiglu<<<(nH4 + 255) / 256, 256>>>(sg, su, nH4);

    k_gemm2<<<(MTOT / 128) * (HIDDEN / 64), 256>>>();

    const int nO4 = (MTOT * HIDDEN) / 4;
    k_down_scale<<<(nO4 + 255) / 256, 256>>>(sd, out, nO4);
}

// round 9
// speedup vs baseline: 1.1871x; 1.1871x over previous
#include <cuda_runtime.h>
#include <cuda_fp16.h>
#include <mma.h>
#include <cstdint>
#include <cstddef>

using namespace nvcuda;

#define HIDDEN 4096
#define INTER  11008
#define MTOT   8192   // B*S

// ---------------- static device scratch ------------------------------------
__device__ __align__(16) __half g_wg[(size_t)INTER * HIDDEN];
__device__ __align__(16) __half g_wu[(size_t)INTER * HIDDEN];
__device__ __align__(16) __half g_wd[(size_t)HIDDEN * INTER];
__device__ __align__(16) __half g_x [(size_t)MTOT  * HIDDEN];
__device__ __align__(16) __half g_h [(size_t)MTOT  * INTER];   // silu(g)*u/16 fp16

// ---------------- conversion kernels ---------------------------------------
__global__ void k_i32_to_h(const int* __restrict__ in, __half* __restrict__ out, int n8) {
    int i = blockIdx.x * blockDim.x + threadIdx.x;
    if (i >= n8) return;
    int4 a = reinterpret_cast<const int4*>(in)[2 * i];
    int4 b = reinterpret_cast<const int4*>(in)[2 * i + 1];
    union { __half h[8]; float4 f; } O;
    O.h[0] = __int2half_rn(a.x); O.h[1] = __int2half_rn(a.y);
    O.h[2] = __int2half_rn(a.z); O.h[3] = __int2half_rn(a.w);
    O.h[4] = __int2half_rn(b.x); O.h[5] = __int2half_rn(b.y);
    O.h[6] = __int2half_rn(b.z); O.h[7] = __int2half_rn(b.w);
    reinterpret_cast<float4*>(out)[i] = O.f;
}

__global__ void k_f32_to_h(const float* __restrict__ in, __half* __restrict__ out, int n8) {
    int i = blockIdx.x * blockDim.x + threadIdx.x;
    if (i >= n8) return;
    float4 a = reinterpret_cast<const float4*>(in)[2 * i];
    float4 b = reinterpret_cast<const float4*>(in)[2 * i + 1];
    union { __half h[8]; float4 f; } O;
    O.h[0] = __float2half(a.x); O.h[1] = __float2half(a.y);
    O.h[2] = __float2half(a.z); O.h[3] = __float2half(a.w);
    O.h[4] = __float2half(b.x); O.h[5] = __float2half(b.y);
    O.h[6] = __float2half(b.z); O.h[7] = __float2half(b.w);
    reinterpret_cast<float4*>(out)[i] = O.f;
}

// ---------------- helpers ---------------------------------------------------
__device__ __forceinline__ void cp_async16(void* sdst, const void* gsrc) {
    uint32_t s = (uint32_t)__cvta_generic_to_shared(sdst);
    asm volatile("cp.async.cg.shared.global [%0], [%1], 16;\n" :: "r"(s), "l"(gsrc));
}
__device__ __forceinline__ void cp_commit() { asm volatile("cp.async.commit_group;\n"); }
__device__ __forceinline__ void cp_wait0()  { asm volatile("cp.async.wait_group 0;\n"); }

__device__ __forceinline__ void tile_map(int bid, int nTiles, int GM, int& m, int& n) {
    int per_panel = GM * nTiles;
    int panel = bid / per_panel;
    int rem   = bid - panel * per_panel;
    n = rem / GM;
    m = panel * GM + (rem - n * GM);
}

// ---------------- GEMM1: gate+up fused, SwiGLU epilogue ---------------------
// CTA 128(M) x 64(N), 8 warps = 4(M) x 2(N), warp 32x32 (2x2 wmma), k-step 64.
// 2-stage cp.async pipeline. Dynamic smem: 2 * (128+64+64)*72 halves = 72 KB.
#define S1_H ((128 + 64 + 64) * 72)

__global__ __launch_bounds__(256, 2)
void k_gemm_swiglu(const float* __restrict__ s_gate, const float* __restrict__ s_up) {
    extern __shared__ __half dyn1[];

    const int tid = threadIdx.x;
    const int wid = tid >> 5;
    const int wm  = wid >> 1, wn = wid & 1;

    int mTile, nTile;
    tile_map(blockIdx.x, INTER / 64, 16, mTile, nTile);
    const int mBase = mTile * 128;
    const int nBase = nTile * 64;

    wmma::fragment<wmma::accumulator, 16, 16, 16, float> accg[2][2], accu[2][2];
#pragma unroll
    for (int i = 0; i < 2; i++)
#pragma unroll
        for (int j = 0; j < 2; j++) { wmma::fill_fragment(accg[i][j], 0.0f); wmma::fill_fragment(accu[i][j], 0.0f); }

    const int ldv = HIDDEN / 8;
    const float4* gAv  = reinterpret_cast<const float4*>(g_x)  + (size_t)mBase * ldv;
    const float4* gBgv = reinterpret_cast<const float4*>(g_wg) + (size_t)nBase * ldv;
    const float4* gBuv = reinterpret_cast<const float4*>(g_wu) + (size_t)nBase * ldv;

    const int r4 = tid >> 3, c4 = tid & 7;   // per-thread chunk coords (8 chunks/row)

    auto prefetch = [&](int kt, int stage) {
        __half* sA  = dyn1 + stage * S1_H;
        __half* sBg = sA + 128 * 72;
        __half* sBu = sBg + 64 * 72;
        const int kc = kt * 8;  // float4 offset in k
#pragma unroll
        for (int j = 0; j < 4; j++) {
            int r = r4 + j * 32;
            cp_async16(sA + r * 72 + c4 * 8, gAv + (size_t)r * ldv + kc + c4);
        }
#pragma unroll
        for (int j = 0; j < 2; j++) {
            int r = r4 + j * 32;
            cp_async16(sBg + r * 72 + c4 * 8, gBgv + (size_t)r * ldv + kc + c4);
            cp_async16(sBu + r * 72 + c4 * 8, gBuv + (size_t)r * ldv + kc + c4);
        }
        cp_commit();
    };

    const int NK = HIDDEN / 64;  // 64
    prefetch(0, 0);

    for (int kt = 0; kt < NK; kt++) {
        cp_wait0();
        __syncthreads();
        if (kt + 1 < NK) prefetch(kt + 1, (kt + 1) & 1);

        __half* sA  = dyn1 + (kt & 1) * S1_H;
        __half* sBg = sA + 128 * 72;
        __half* sBu = sBg + 64 * 72;

#pragma unroll
        for (int ks = 0; ks < 64; ks += 16) {
            wmma::fragment<wmma::matrix_a, 16, 16, 16, __half, wmma::row_major> af[2];
#pragma unroll
            for (int mt = 0; mt < 2; mt++)
                wmma::load_matrix_sync(af[mt], sA + (wm * 32 + mt * 16) * 72 + ks, 72);
#pragma unroll
            for (int nt = 0; nt < 2; nt++) {
                wmma::fragment<wmma::matrix_b, 16, 16, 16, __half, wmma::col_major> bg, bu;
                wmma::load_matrix_sync(bg, sBg + (wn * 32 + nt * 16) * 72 + ks, 72);
                wmma::load_matrix_sync(bu, sBu + (wn * 32 + nt * 16) * 72 + ks, 72);
#pragma unroll
                for (int mt = 0; mt < 2; mt++) {
                    wmma::mma_sync(accg[mt][nt], af[mt], bg, accg[mt][nt]);
                    wmma::mma_sync(accu[mt][nt], af[mt], bu, accu[mt][nt]);
                }
            }
        }
        __syncthreads();   // all warps done with this stage before it is re-filled
    }

    // ---- fused epilogue: stage accumulators through smem (no fragment indexing)
    float* sg_ = reinterpret_cast<float*>(dyn1);            // 128 x 68
    float* su_ = sg_ + 128 * 68;                            // 128 x 68
#pragma unroll
    for (int mt = 0; mt < 2; mt++)
#pragma unroll
        for (int nt = 0; nt < 2; nt++) {
            int r0 = wm * 32 + mt * 16, c0 = wn * 32 + nt * 16;
            wmma::store_matrix_sync(sg_ + r0 * 68 + c0, accg[mt][nt], 68, wmma::mem_row_major);
            wmma::store_matrix_sync(su_ + r0 * 68 + c0, accu[mt][nt], 68, wmma::mem_row_major);
        }
    __syncthreads();

#pragma unroll
    for (int j = 0; j < 8; j++) {
        int idx = tid + j * 256;          // 2048 float4 chunks
        int r = idx >> 4, cc = idx & 15;
        float4 g = *reinterpret_cast<const float4*>(sg_ + r * 68 + cc * 4);
        float4 u = *reinterpret_cast<const float4*>(su_ + r * 68 + cc * 4);
        int c0 = nBase + cc * 4;
        float g0 = g.x * s_gate[c0],     u0 = u.x * s_up[c0];
        float g1 = g.y * s_gate[c0 + 1], u1 = u.y * s_up[c0 + 1];
        float g2 = g.z * s_gate[c0 + 2], u2 = u.z * s_up[c0 + 2];
        float g3 = g.w * s_gate[c0 + 3], u3 = u.w * s_up[c0 + 3];
        float h0 = (g0 / (1.f + __expf(-g0))) * u0 * 0.0625f;
        float h1 = (g1 / (1.f + __expf(-g1))) * u1 * 0.0625f;
        float h2 = (g2 / (1.f + __expf(-g2))) * u2 * 0.0625f;
        float h3 = (g3 / (1.f + __expf(-g3))) * u3 * 0.0625f;
        union { __half h[4]; uint2 v; } O;
        O.h[0] = __float2half(h0); O.h[1] = __float2half(h1);
        O.h[2] = __float2half(h2); O.h[3] = __float2half(h3);
        *reinterpret_cast<uint2*>(&g_h[(size_t)(mBase + r) * INTER + c0]) = O.v;
    }
}

// ---------------- GEMM2: down proj, fused scale epilogue --------------------
#define S2_H ((128 + 64) * 72)

__global__ __launch_bounds__(256, 2)
void k_gemm_down(const float* __restrict__ s_down, float* __restrict__ out) {
    extern __shared__ __half dyn2[];

    const int tid = threadIdx.x;
    const int wid = tid >> 5;
    const int wm  = wid >> 1, wn = wid & 1;

    int mTile, nTile;
    tile_map(blockIdx.x, HIDDEN / 64, 16, mTile, nTile);
    const int mBase = mTile * 128;
    const int nBase = nTile * 64;

    wmma::fragment<wmma::accumulator, 16, 16, 16, float> acc[2][2];
#pragma unroll
    for (int i = 0; i < 2; i++)
#pragma unroll
        for (int j = 0; j < 2; j++) wmma::fill_fragment(acc[i][j], 0.0f);

    const int ldv = INTER / 8;  // 1376
    const float4* gAv = reinterpret_cast<const float4*>(g_h)  + (size_t)mBase * ldv;
    const float4* gBv = reinterpret_cast<const float4*>(g_wd) + (size_t)nBase * ldv;

    const int r4 = tid >> 3, c4 = tid & 7;

    auto prefetch = [&](int kt, int stage) {
        __half* sA = dyn2 + stage * S2_H;
        __half* sB = sA + 128 * 72;
        const int kc = kt * 8;
#pragma unroll
        for (int j = 0; j < 4; j++) {
            int r = r4 + j * 32;
            cp_async16(sA + r * 72 + c4 * 8, gAv + (size_t)r * ldv + kc + c4);
        }
#pragma unroll
        for (int j = 0; j < 2; j++) {
            int r = r4 + j * 32;
            cp_async16(sB + r * 72 + c4 * 8, gBv + (size_t)r * ldv + kc + c4);
        }
        cp_commit();
    };

    const int NK = INTER / 64;  // 172
    prefetch(0, 0);

    for (int kt = 0; kt < NK; kt++) {
        cp_wait0();
        __syncthreads();
        if (kt + 1 < NK) prefetch(kt + 1, (kt + 1) & 1);

        __half* sA = dyn2 + (kt & 1) * S2_H;
        __half* sB = sA + 128 * 72;

#pragma unroll
        for (int ks = 0; ks < 64; ks += 16) {
            wmma::fragment<wmma::matrix_a, 16, 16, 16, __half, wmma::row_major> af[2];
#pragma unroll
            for (int mt = 0; mt < 2; mt++)
                wmma::load_matrix_sync(af[mt], sA + (wm * 32 + mt * 16) * 72 + ks, 72);
#pragma unroll
            for (int nt = 0; nt < 2; nt++) {
                wmma::fragment<wmma::matrix_b, 16, 16, 16, __half, wmma::col_major> bf;
                wmma::load_matrix_sync(bf, sB + (wn * 32 + nt * 16) * 72 + ks, 72);
#pragma unroll
                for (int mt = 0; mt < 2; mt++)
                    wmma::mma_sync(acc[mt][nt], af[mt], bf, acc[mt][nt]);
            }
        }
        __syncthreads();
    }

    // ---- fused epilogue through smem
    float* so_ = reinterpret_cast<float*>(dyn2);            // 128 x 68
#pragma unroll
    for (int mt = 0; mt < 2; mt++)
#pragma unroll
        for (int nt = 0; nt < 2; nt++) {
            int r0 = wm * 32 + mt * 16, c0 = wn * 32 + nt * 16;
            wmma::store_matrix_sync(so_ + r0 * 68 + c0, acc[mt][nt], 68, wmma::mem_row_major);
        }
    __syncthreads();

#pragma unroll
    for (int j = 0; j < 8; j++) {
        int idx = tid + j * 256;
        int r = idx >> 4, cc = idx & 15;
        float4 v = *reinterpret_cast<const float4*>(so_ + r * 68 + cc * 4);
        int c0 = nBase + cc * 4;
        float4 o;
        o.x = v.x * s_down[c0]     * 16.f;
        o.y = v.y * s_down[c0 + 1] * 16.f;
        o.z = v.z * s_down[c0 + 2] * 16.f;
        o.w = v.w * s_down[c0 + 3] * 16.f;
        *reinterpret_cast<float4*>(&out[(size_t)(mBase + r) * HIDDEN + c0]) = o;
    }
}

// ---------------- launch -----------------------------------------------------
// Inputs by element count (dict order, x first). Weights are int32 (upcast int8).
extern "C" void kernel_launch(void* const* d_in, const int* in_sizes, int n_in,
                              void* d_out, int out_size) {
    int ix = -1, isd = -1;
    int is_[2]; int ns = 0;
    int iw_[3]; int nw = 0;
    for (int i = 0; i < n_in; i++) {
        int sz = in_sizes[i];
        if (sz == MTOT * HIDDEN)       ix = i;
        else if (sz == HIDDEN)         isd = i;
        else if (sz == INTER)          { if (ns < 2) is_[ns++] = i; }
        else if (sz == INTER * HIDDEN) { if (nw < 3) iw_[nw++] = i; }
    }
    bool dict_order = (ix == 0);
    int iwg = dict_order ? iw_[0] : iw_[1];
    int iwu = dict_order ? iw_[1] : iw_[2];
    int iwd = dict_order ? iw_[2] : iw_[0];

    const float* x  = (const float*)d_in[ix];
    const int*   wg = (const int*)  d_in[iwg];
    const float* sg = (const float*)d_in[is_[0]];
    const int*   wu = (const int*)  d_in[iwu];
    const float* su = (const float*)d_in[is_[1]];
    const int*   wd = (const int*)  d_in[iwd];
    const float* sd = (const float*)d_in[isd];
    float* out = (float*)d_out;

    void *pwg, *pwu, *pwd, *px;
    cudaGetSymbolAddress(&pwg, g_wg);
    cudaGetSymbolAddress(&pwu, g_wu);
    cudaGetSymbolAddress(&pwd, g_wd);
    cudaGetSymbolAddress(&px,  g_x);

    static bool attr_done = false;
    if (!attr_done) {
        cudaFuncSetAttribute(k_gemm_swiglu, cudaFuncAttributeMaxDynamicSharedMemorySize, 2 * S1_H * 2);
        cudaFuncSetAttribute(k_gemm_down,   cudaFuncAttributeMaxDynamicSharedMemorySize, 2 * S2_H * 2);
        attr_done = true;
    }

    const int nW8 = (INTER * HIDDEN) / 8;
    const int nX8 = (MTOT * HIDDEN) / 8;
    k_i32_to_h<<<(nW8 + 255) / 256, 256>>>(wg, (__half*)pwg, nW8);
    k_i32_to_h<<<(nW8 + 255) / 256, 256>>>(wu, (__half*)pwu, nW8);
    k_i32_to_h<<<(nW8 + 255) / 256, 256>>>(wd, (__half*)pwd, nW8);
    k_f32_to_h<<<(nX8 + 255) / 256, 256>>>(x, (__half*)px, nX8);

    k_gemm_swiglu<<<(MTOT / 128) * (INTER / 64), 256, 2 * S1_H * 2>>>(sg, su);
    k_gemm_down  <<<(MTOT / 128) * (HIDDEN / 64), 256, 2 * S2_H * 2>>>(sd, out);
}